// round 1
// baseline (speedup 1.0000x reference)
#include <cuda_runtime.h>
#include <cuda_bf16.h>

// InputSequenceNormalization: x [B, F, T] fp32, lengths [B] fp32 (relative).
// Per (b,f) row: n = round(lengths[b]*T); mean/std over t < n (std unbiased,
// ddof=1, clamped to EPS); normalize ALL T frames.
//
// Single-pass, register-resident: each block owns one row (T=8000 floats =
// 2000 float4). 256 threads x 8 float4 each. Load once, reduce (sum, sumsq),
// normalize from registers, store once. Traffic = 2 * 163.8 MB.

#define T_LEN 8000
#define TV    2000          // float4 elements per row
#define NTHREADS 256
#define KCHUNK 8            // ceil(2000/256)
#define EPS_STD 1e-10f

__device__ __forceinline__ void warp_reduce2(float& s, float& sq) {
    #pragma unroll
    for (int o = 16; o > 0; o >>= 1) {
        s  += __shfl_down_sync(0xffffffffu, s,  o);
        sq += __shfl_down_sync(0xffffffffu, sq, o);
    }
}

__global__ __launch_bounds__(NTHREADS)
void isn_kernel(const float* __restrict__ x,
                const float* __restrict__ lengths,
                float* __restrict__ out,
                int F) {
    const int row = blockIdx.x;            // b * F + f
    const int b   = row / F;
    const size_t base = (size_t)row * T_LEN;
    const float4* __restrict__ xin = reinterpret_cast<const float4*>(x + base);
    float4* __restrict__ xout      = reinterpret_cast<float4*>(out + base);

    const int n = (int)rintf(lengths[b] * (float)T_LEN);   // round-half-even

    float4 v[KCHUNK];
    float s = 0.0f, sq = 0.0f;

    #pragma unroll
    for (int k = 0; k < KCHUNK; k++) {
        const int j = threadIdx.x + k * NTHREADS;
        if (j < TV) {
            float4 t = xin[j];
            v[k] = t;
            const int t0 = 4 * j;
            // branchless per-element mask (n >= 4000 so most are valid)
            float m0 = (t0 + 0 < n) ? 1.0f : 0.0f;
            float m1 = (t0 + 1 < n) ? 1.0f : 0.0f;
            float m2 = (t0 + 2 < n) ? 1.0f : 0.0f;
            float m3 = (t0 + 3 < n) ? 1.0f : 0.0f;
            float a = t.x * m0, c = t.y * m1, d = t.z * m2, e = t.w * m3;
            s  += a + c + d + e;
            sq += a * t.x + c * t.y + d * t.z + e * t.w;
        }
    }

    // block reduction: warp shuffle, then cross-warp via smem
    __shared__ float ssum[NTHREADS / 32];
    __shared__ float ssq [NTHREADS / 32];
    __shared__ float sstat[2];   // mean, inv_std

    const int lane = threadIdx.x & 31;
    const int wid  = threadIdx.x >> 5;

    warp_reduce2(s, sq);
    if (lane == 0) { ssum[wid] = s; ssq[wid] = sq; }
    __syncthreads();

    if (wid == 0) {
        s  = (lane < NTHREADS / 32) ? ssum[lane] : 0.0f;
        sq = (lane < NTHREADS / 32) ? ssq[lane]  : 0.0f;
        warp_reduce2(s, sq);
        if (lane == 0) {
            const float nf   = (float)n;
            const float mean = s / nf;
            float var = (sq - s * s / nf) / (nf - 1.0f);
            var = fmaxf(var, 0.0f);
            const float stdv = fmaxf(sqrtf(var), EPS_STD);
            sstat[0] = mean;
            sstat[1] = 1.0f / stdv;
        }
    }
    __syncthreads();

    const float mean = sstat[0];
    const float inv  = sstat[1];

    #pragma unroll
    for (int k = 0; k < KCHUNK; k++) {
        const int j = threadIdx.x + k * NTHREADS;
        if (j < TV) {
            float4 t = v[k];
            float4 o;
            o.x = (t.x - mean) * inv;
            o.y = (t.y - mean) * inv;
            o.z = (t.z - mean) * inv;
            o.w = (t.w - mean) * inv;
            xout[j] = o;
        }
    }
}

extern "C" void kernel_launch(void* const* d_in, const int* in_sizes, int n_in,
                              void* d_out, int out_size) {
    const float* x       = (const float*)d_in[0];
    const float* lengths = (const float*)d_in[1];
    float* out           = (float*)d_out;

    const int B    = in_sizes[1];
    const int rows = in_sizes[0] / T_LEN;     // B * F
    const int F    = rows / B;

    isn_kernel<<<rows, NTHREADS>>>(x, lengths, out, F);
}